// round 6
// baseline (speedup 1.0000x reference)
#include <cuda_runtime.h>
#include <cuda_bf16.h>
#include <mma.h>
#include <cstdint>

using namespace nvcuda;

// ---------------------------------------------------------------------------
// Problem constants
// ---------------------------------------------------------------------------
#define EMBED   256
#define HEADS   8
#define LEVELS  4
#define POINTS  4
#define DIM     32
#define BS      2
#define NQ      13294
#define MTOT    (BS * NQ)       // 26588
#define NBIG    640             // value(256) | off(256) | attn(128)

__device__ __forceinline__ int lvl_H(int l) { return l == 0 ? 100 : l == 1 ? 50 : l == 2 ? 25 : 13; }
__device__ __forceinline__ int lvl_W(int l) { return l == 0 ? 100 : l == 1 ? 50 : l == 2 ? 25 : 13; }
__device__ __forceinline__ int lvl_S(int l) { return l == 0 ? 0 : l == 1 ? 10000 : l == 2 ? 12500 : 13125; }

// ---------------------------------------------------------------------------
// Scratch
// ---------------------------------------------------------------------------
__device__ float          g_big  [(size_t)MTOT * NBIG];  // fused value|off|attn (fp32)
__device__ __nv_bfloat16  g_qhi  [(size_t)MTOT * 256];
__device__ __nv_bfloat16  g_qlo  [(size_t)MTOT * 256];
__device__ __nv_bfloat16  g_ahi  [(size_t)MTOT * 256];   // sampler output hi
__device__ __nv_bfloat16  g_alo  [(size_t)MTOT * 256];   // sampler output lo
__device__ __nv_bfloat16  g_Wbh  [256 * NBIG];
__device__ __nv_bfloat16  g_Wbl  [256 * NBIG];
__device__ __nv_bfloat16  g_Woh  [256 * 256];
__device__ __nv_bfloat16  g_Wol  [256 * 256];
__device__ float          g_bp   [NBIG];

// ---------------------------------------------------------------------------
// Helpers
// ---------------------------------------------------------------------------
__device__ __forceinline__ void bf16split(float x, __nv_bfloat16& h, __nv_bfloat16& l) {
    h = __float2bfloat16(x);
    l = __float2bfloat16(x - __bfloat162float(h));
}
__device__ __forceinline__ uint32_t pack2(__nv_bfloat16 a, __nv_bfloat16 b) {
    __nv_bfloat162 t(a, b);
    return *reinterpret_cast<uint32_t*>(&t);
}
__device__ __forceinline__ void cp16(uint32_t dst, const void* src, int sz) {
    asm volatile("cp.async.cg.shared.global [%0], [%1], 16, %2;\n"
                 :: "r"(dst), "l"(src), "r"(sz) : "memory");
}
#define CP_COMMIT() asm volatile("cp.async.commit_group;" ::: "memory")
#define CP_WAIT1()  asm volatile("cp.async.wait_group 1;" ::: "memory")
#define CP_WAIT0()  asm volatile("cp.async.wait_group 0;" ::: "memory")

// ---------------------------------------------------------------------------
// Pack weights into bf16 hi/lo
// ---------------------------------------------------------------------------
__global__ void pack_weights(const float* __restrict__ Wv, const float* __restrict__ bv,
                             const float* __restrict__ Wo, const float* __restrict__ bo,
                             const float* __restrict__ Wa, const float* __restrict__ ba,
                             const float* __restrict__ Wout,
                             __nv_bfloat16* __restrict__ Wbh, __nv_bfloat16* __restrict__ Wbl,
                             __nv_bfloat16* __restrict__ Woh, __nv_bfloat16* __restrict__ Wol,
                             float* __restrict__ bp)
{
    const int i = blockIdx.x * 256 + threadIdx.x;
    if (i < 256 * NBIG) {
        const int r = i / NBIG, c = i - r * NBIG;
        float w;
        if (c < 256)      w = Wv[r * 256 + c];
        else if (c < 512) w = Wo[r * 256 + (c - 256)];
        else              w = Wa[r * 128 + (c - 512)];
        __nv_bfloat16 h, l; bf16split(w, h, l);
        Wbh[i] = h; Wbl[i] = l;
    }
    if (i < 256 * 256) {
        __nv_bfloat16 h, l; bf16split(Wout[i], h, l);
        Woh[i] = h; Wol[i] = l;
    }
    if (i < NBIG) bp[i] = (i < 256) ? bv[i] : (i < 512) ? bo[i - 256] : ba[i - 512];
}

// ---------------------------------------------------------------------------
// query fp32 -> bf16 hi/lo
// ---------------------------------------------------------------------------
__global__ void convert_query(const float4* __restrict__ q,
                              __nv_bfloat16* __restrict__ qh,
                              __nv_bfloat16* __restrict__ ql)
{
    const int i = blockIdx.x * 256 + threadIdx.x;
    const float4 v = q[i];
    __nv_bfloat16 h0, h1, h2, h3, l0, l1, l2, l3;
    bf16split(v.x, h0, l0); bf16split(v.y, h1, l1);
    bf16split(v.z, h2, l2); bf16split(v.w, h3, l3);
    reinterpret_cast<uint2*>(qh)[i] = make_uint2(pack2(h0, h1), pack2(h2, h3));
    reinterpret_cast<uint2*>(ql)[i] = make_uint2(pack2(l0, l1), pack2(l2, l3));
}

// ---------------------------------------------------------------------------
// Tensor-core GEMM, 3-pass bf16 split. All 12 operand fragments loaded ONCE
// per k-iter, then 24 MMAs with no smem reloads.
// ---------------------------------------------------------------------------
#define LDA 24
#define LDB 136
#define A_BUF_BYTES (128 * LDA * 2)   // 6144
#define B_BUF_BYTES (16 * LDB * 2)    // 4352
#define OFF_AH 0
#define OFF_AL (2 * A_BUF_BYTES)
#define OFF_BH (4 * A_BUF_BYTES)
#define OFF_BL (OFF_BH + 2 * B_BUF_BYTES)
#define SMEM_GEMM (OFF_BL + 2 * B_BUF_BYTES)   // 41984

__global__ __launch_bounds__(256, 2) void gemm_bf3(
    const __nv_bfloat16* __restrict__ Ah, const __nv_bfloat16* __restrict__ Al,
    const __nv_bfloat16* __restrict__ Bh, const __nv_bfloat16* __restrict__ Bl,
    const float* __restrict__ bias, const float* __restrict__ resid,
    float* __restrict__ C, int M, int N, int K)
{
    __shared__ char smem[SMEM_GEMM];
    const uint32_t sbase = (uint32_t)__cvta_generic_to_shared(smem);

    const int t    = threadIdx.x;
    const int w    = t >> 5;
    const int lane = t & 31;
    const int wm   = w >> 2;
    const int wn   = w & 3;
    const int gn   = blockIdx.x * 128;
    const int gm   = blockIdx.y * 128;

    const int arow  = t >> 1;
    const int apart = (t & 1) * 8;
    const int ga    = min(gm + arow, M - 1);
    const int apred = (gm + arow < M) ? 16 : 0;
    const int brow  = t >> 4;
    const int bcol  = (t & 15) * 8;

    const uint32_t dAh = sbase + OFF_AH + (uint32_t)(arow * LDA + apart) * 2;
    const uint32_t dAl = sbase + OFF_AL + (uint32_t)(arow * LDA + apart) * 2;
    const uint32_t dBh = sbase + OFF_BH + (uint32_t)(brow * LDB + bcol) * 2;
    const uint32_t dBl = sbase + OFF_BL + (uint32_t)(brow * LDB + bcol) * 2;

    wmma::fragment<wmma::accumulator, 16, 16, 16, float> acc[4][2];
#pragma unroll
    for (int i = 0; i < 4; i++)
#pragma unroll
        for (int j = 0; j < 2; j++) wmma::fill_fragment(acc[i][j], 0.f);

    cp16(dAh, Ah + (size_t)ga * K + apart, apred);
    cp16(dAl, Al + (size_t)ga * K + apart, apred);
    cp16(dBh, Bh + (size_t)brow * N + gn + bcol, 16);
    cp16(dBl, Bl + (size_t)brow * N + gn + bcol, 16);
    CP_COMMIT();

    const int niter = K / 16;
    int buf = 0;
    for (int it = 0; it < niter; it++) {
        if (it + 1 < niter) {
            const int kt = (it + 1) * 16;
            const uint32_t bo = (buf ^ 1);
            cp16(dAh + bo * A_BUF_BYTES, Ah + (size_t)ga * K + kt + apart, apred);
            cp16(dAl + bo * A_BUF_BYTES, Al + (size_t)ga * K + kt + apart, apred);
            cp16(dBh + bo * B_BUF_BYTES, Bh + (size_t)(kt + brow) * N + gn + bcol, 16);
            cp16(dBl + bo * B_BUF_BYTES, Bl + (size_t)(kt + brow) * N + gn + bcol, 16);
            CP_COMMIT();
            CP_WAIT1();
        } else {
            CP_WAIT0();
        }
        __syncthreads();

        const __nv_bfloat16* pAh = reinterpret_cast<const __nv_bfloat16*>(smem + OFF_AH + buf * A_BUF_BYTES) + wm * 64 * LDA;
        const __nv_bfloat16* pAl = reinterpret_cast<const __nv_bfloat16*>(smem + OFF_AL + buf * A_BUF_BYTES) + wm * 64 * LDA;
        const __nv_bfloat16* pBh = reinterpret_cast<const __nv_bfloat16*>(smem + OFF_BH + buf * B_BUF_BYTES) + wn * 32;
        const __nv_bfloat16* pBl = reinterpret_cast<const __nv_bfloat16*>(smem + OFF_BL + buf * B_BUF_BYTES) + wn * 32;

        wmma::fragment<wmma::matrix_a, 16, 16, 16, __nv_bfloat16, wmma::row_major> ah[4], al4[4];
        wmma::fragment<wmma::matrix_b, 16, 16, 16, __nv_bfloat16, wmma::row_major> bh2[2], bl2[2];

#pragma unroll
        for (int i = 0; i < 4; i++) wmma::load_matrix_sync(ah[i],  pAh + i * 16 * LDA, LDA);
#pragma unroll
        for (int i = 0; i < 4; i++) wmma::load_matrix_sync(al4[i], pAl + i * 16 * LDA, LDA);
#pragma unroll
        for (int j = 0; j < 2; j++) wmma::load_matrix_sync(bh2[j], pBh + j * 16, LDB);
#pragma unroll
        for (int j = 0; j < 2; j++) wmma::load_matrix_sync(bl2[j], pBl + j * 16, LDB);

#pragma unroll
        for (int i = 0; i < 4; i++)
#pragma unroll
            for (int j = 0; j < 2; j++) wmma::mma_sync(acc[i][j], ah[i],  bh2[j], acc[i][j]);
#pragma unroll
        for (int i = 0; i < 4; i++)
#pragma unroll
            for (int j = 0; j < 2; j++) wmma::mma_sync(acc[i][j], ah[i],  bl2[j], acc[i][j]);
#pragma unroll
        for (int i = 0; i < 4; i++)
#pragma unroll
            for (int j = 0; j < 2; j++) wmma::mma_sync(acc[i][j], al4[i], bh2[j], acc[i][j]);

        __syncthreads();
        buf ^= 1;
    }

    // epilogue via per-warp smem staging
    float* stg = reinterpret_cast<float*>(smem) + w * 256;
    const int r  = lane >> 1;
    const int ch = (lane & 1) * 8;
#pragma unroll
    for (int i = 0; i < 4; i++) {
#pragma unroll
        for (int j = 0; j < 2; j++) {
            wmma::store_matrix_sync(stg, acc[i][j], 16, wmma::mem_row_major);
            __syncwarp();
            const int row = gm + wm * 64 + i * 16 + r;
            const int col = gn + wn * 32 + j * 16 + ch;
            if (row < M) {
                float4 o0 = *reinterpret_cast<const float4*>(&stg[r * 16 + ch]);
                float4 o1 = *reinterpret_cast<const float4*>(&stg[r * 16 + ch + 4]);
                const float4 bi0 = *reinterpret_cast<const float4*>(bias + col);
                const float4 bi1 = *reinterpret_cast<const float4*>(bias + col + 4);
                o0.x += bi0.x; o0.y += bi0.y; o0.z += bi0.z; o0.w += bi0.w;
                o1.x += bi1.x; o1.y += bi1.y; o1.z += bi1.z; o1.w += bi1.w;
                if (resid) {
                    const float4 r0 = *reinterpret_cast<const float4*>(resid + (size_t)row * N + col);
                    const float4 r1 = *reinterpret_cast<const float4*>(resid + (size_t)row * N + col + 4);
                    o0.x += r0.x; o0.y += r0.y; o0.z += r0.z; o0.w += r0.w;
                    o1.x += r1.x; o1.y += r1.y; o1.z += r1.z; o1.w += r1.w;
                }
                *reinterpret_cast<float4*>(C + (size_t)row * N + col)     = o0;
                *reinterpret_cast<float4*>(C + (size_t)row * N + col + 4) = o1;
            }
            __syncwarp();
        }
    }
}

// ---------------------------------------------------------------------------
// Sampler: phase 1 precompute -> smem; phase 2 pipelined gathers
// (2 samples per step, 8 LDG.128 in flight).
// ---------------------------------------------------------------------------
#define QPB    4
#define HSTR   132
#define QSTR   (8 * HSTR)

__global__ __launch_bounds__(256, 3) void msda_sample(
    const float* __restrict__ G,      // [M,640] value|off|attn (fp32)
    const float* __restrict__ refp,   // [M,4,2]
    __nv_bfloat16* __restrict__ ahi,
    __nv_bfloat16* __restrict__ alo)
{
    __shared__ float sp[QPB * QSTR];

    const int tid = threadIdx.x;
    const int m0  = blockIdx.x * QPB;
    const unsigned FULL = 0xffffffffu;

#pragma unroll
    for (int rep = 0; rep < 2; rep++) {
        const int p   = tid + rep * 256;
        const int q   = p >> 7;
        const int rem = p & 127;
        const int h   = rem >> 4;
        const int s   = rem & 15;
        const int m   = m0 + q;

        const float lg = G[m * NBIG + 512 + rem];
        float mx = lg;
#pragma unroll
        for (int o = 8; o; o >>= 1) mx = fmaxf(mx, __shfl_xor_sync(FULL, mx, o));
        const float e = expf(lg - mx);
        float sum = e;
#pragma unroll
        for (int o = 8; o; o >>= 1) sum += __shfl_xor_sync(FULL, sum, o);
        const float aw = e / sum;

        const int l = s >> 2, pp = s & 3;
        const int W = lvl_W(l), H = lvl_H(l), st = lvl_S(l);
        const float rx = refp[m * 8 + l * 2 + 0];
        const float ry = refp[m * 8 + l * 2 + 1];
        const float ox = G[m * NBIG + 256 + h * 32 + l * 8 + pp * 2 + 0];
        const float oy = G[m * NBIG + 256 + h * 32 + l * 8 + pp * 2 + 1];
        const float x = fmaf(rx, (float)W, ox) - 0.5f;
        const float y = fmaf(ry, (float)H, oy) - 0.5f;
        const float xf = floorf(x), yf = floorf(y);
        const int ix = (int)xf, iy = (int)yf;
        const float lx = x - xf, ly = y - yf;
        const bool x0ok = (ix >= 0)  & (ix < W);
        const bool x1ok = (ix >= -1) & (ix < W - 1);
        const bool y0ok = (iy >= 0)  & (iy < H);
        const bool y1ok = (iy >= -1) & (iy < H - 1);
        const float wx0 = 1.f - lx, wy0 = 1.f - ly;
        const float w00 = (x0ok & y0ok) ? wy0 * wx0 * aw : 0.f;
        const float w01 = (x1ok & y0ok) ? wy0 * lx  * aw : 0.f;
        const float w10 = (x0ok & y1ok) ? ly  * wx0 * aw : 0.f;
        const float w11 = (x1ok & y1ok) ? ly  * lx  * aw : 0.f;
        const int xc0 = min(max(ix, 0), W - 1);
        const int xc1 = min(max(ix + 1, 0), W - 1);
        const int yc0 = min(max(iy, 0), H - 1);
        const int yc1 = min(max(iy + 1, 0), H - 1);
        const int r0 = yc0 * W + st;     // < 13381, fits 15 bits
        const int r1 = yc1 * W + st;
        const int pA = (r0 + xc0) | ((r0 + xc1) << 16);
        const int pB = (r1 + xc0) | ((r1 + xc1) << 16);

        float* dst = &sp[q * QSTR + h * HSTR + s * 8];
        dst[0] = __int_as_float(pA);
        dst[1] = __int_as_float(pB);
        dst[2] = w00; dst[3] = w01; dst[4] = w10; dst[5] = w11;
    }
    __syncthreads();

    const int w    = tid >> 5;
    const int lane = tid & 31;
    const int q    = w >> 1;
    const int head = (w & 1) * 4 + (lane >> 3);
    const int c4   = (lane & 7) * 4;
    const int m    = m0 + q;
    const int b    = (m >= NQ) ? 1 : 0;

    const float* __restrict__ vb  = G + (size_t)b * NQ * NBIG + head * 32 + c4;
    const float* __restrict__ prm = &sp[q * QSTR + head * HSTR];

    float4 av = make_float4(0.f, 0.f, 0.f, 0.f);
#pragma unroll
    for (int s = 0; s < 16; s += 2) {
        // params for 2 samples
        const float4 f1a = *reinterpret_cast<const float4*>(&prm[s * 8]);
        const float4 f2a = *reinterpret_cast<const float4*>(&prm[s * 8 + 4]);
        const float4 f1b = *reinterpret_cast<const float4*>(&prm[s * 8 + 8]);
        const float4 f2b = *reinterpret_cast<const float4*>(&prm[s * 8 + 12]);
        const int ia = __float_as_int(f1a.x);
        const int ib = __float_as_int(f1a.y);
        const int ic = __float_as_int(f1b.x);
        const int id = __float_as_int(f1b.y);
        // 8 independent gathers in flight
        const float4 v0 = *reinterpret_cast<const float4*>(vb + (ia & 0xffff) * NBIG);
        const float4 v1 = *reinterpret_cast<const float4*>(vb + (ia >> 16)    * NBIG);
        const float4 v2 = *reinterpret_cast<const float4*>(vb + (ib & 0xffff) * NBIG);
        const float4 v3 = *reinterpret_cast<const float4*>(vb + (ib >> 16)    * NBIG);
        const float4 v4 = *reinterpret_cast<const float4*>(vb + (ic & 0xffff) * NBIG);
        const float4 v5 = *reinterpret_cast<const float4*>(vb + (ic >> 16)    * NBIG);
        const float4 v6 = *reinterpret_cast<const float4*>(vb + (id & 0xffff) * NBIG);
        const float4 v7 = *reinterpret_cast<const float4*>(vb + (id >> 16)    * NBIG);

        av.x = fmaf(f1a.z, v0.x, av.x); av.y = fmaf(f1a.z, v0.y, av.y);
        av.z = fmaf(f1a.z, v0.z, av.z); av.w = fmaf(f1a.z, v0.w, av.w);
        av.x = fmaf(f1a.w, v1.x, av.x); av.y = fmaf(f1a.w, v1.y, av.y);
        av.z = fmaf(f1a.w, v1.z, av.z); av.w = fmaf(f1a.w, v1.w, av.w);
        av.x = fmaf(f2a.x, v2.x, av.x); av.y = fmaf(f2a.x, v2.y, av.y);
        av.z = fmaf(f2a.x, v2.z, av.z); av.w = fmaf(f2a.x, v2.w, av.w);
        av.x = fmaf(f2a.y, v3.x, av.x); av.y = fmaf(f2a.y, v3.y, av.y);
        av.z = fmaf(f2a.y, v3.z, av.z); av.w = fmaf(f2a.y, v3.w, av.w);

        av.x = fmaf(f1b.z, v4.x, av.x); av.y = fmaf(f1b.z, v4.y, av.y);
        av.z = fmaf(f1b.z, v4.z, av.z); av.w = fmaf(f1b.z, v4.w, av.w);
        av.x = fmaf(f1b.w, v5.x, av.x); av.y = fmaf(f1b.w, v5.y, av.y);
        av.z = fmaf(f1b.w, v5.z, av.z); av.w = fmaf(f1b.w, v5.w, av.w);
        av.x = fmaf(f2b.x, v6.x, av.x); av.y = fmaf(f2b.x, v6.y, av.y);
        av.z = fmaf(f2b.x, v6.z, av.z); av.w = fmaf(f2b.x, v6.w, av.w);
        av.x = fmaf(f2b.y, v7.x, av.x); av.y = fmaf(f2b.y, v7.y, av.y);
        av.z = fmaf(f2b.y, v7.z, av.z); av.w = fmaf(f2b.y, v7.w, av.w);
    }

    __nv_bfloat16 h0b, h1b, h2b, h3b, l0b, l1b, l2b, l3b;
    bf16split(av.x, h0b, l0b); bf16split(av.y, h1b, l1b);
    bf16split(av.z, h2b, l2b); bf16split(av.w, h3b, l3b);
    const size_t base = ((size_t)m * 256 + head * 32 + c4) >> 2;
    reinterpret_cast<uint2*>(ahi)[base] = make_uint2(pack2(h0b, h1b), pack2(h2b, h3b));
    reinterpret_cast<uint2*>(alo)[base] = make_uint2(pack2(l0b, l1b), pack2(l2b, l3b));
}

// ---------------------------------------------------------------------------
// Launch
// ---------------------------------------------------------------------------
extern "C" void kernel_launch(void* const* d_in, const int* in_sizes, int n_in,
                              void* d_out, int out_size)
{
    const float* query = (const float*)d_in[0];
    const float* refp  = (const float*)d_in[1];
    const float* Wv    = (const float*)d_in[3];
    const float* bv    = (const float*)d_in[4];
    const float* Wo    = (const float*)d_in[5];
    const float* bo    = (const float*)d_in[6];
    const float* Wa    = (const float*)d_in[7];
    const float* ba    = (const float*)d_in[8];
    const float* Wout  = (const float*)d_in[9];
    const float* bout  = (const float*)d_in[10];
    float*       out   = (float*)d_out;

    float *pg, *pbp;
    __nv_bfloat16 *pqh, *pql, *pah, *pal, *pwbh, *pwbl, *pwoh, *pwol;
    cudaGetSymbolAddress((void**)&pg,   g_big);
    cudaGetSymbolAddress((void**)&pbp,  g_bp);
    cudaGetSymbolAddress((void**)&pqh,  g_qhi);
    cudaGetSymbolAddress((void**)&pql,  g_qlo);
    cudaGetSymbolAddress((void**)&pah,  g_ahi);
    cudaGetSymbolAddress((void**)&pal,  g_alo);
    cudaGetSymbolAddress((void**)&pwbh, g_Wbh);
    cudaGetSymbolAddress((void**)&pwbl, g_Wbl);
    cudaGetSymbolAddress((void**)&pwoh, g_Woh);
    cudaGetSymbolAddress((void**)&pwol, g_Wol);

    const int M = MTOT;
    const int mtiles = (M + 127) / 128;

    pack_weights<<<NBIG, 256>>>(Wv, bv, Wo, bo, Wa, ba, Wout,
                                pwbh, pwbl, pwoh, pwol, pbp);
    convert_query<<<MTOT / 4, 256>>>((const float4*)query, pqh, pql);

    gemm_bf3<<<dim3(NBIG / 128, mtiles), 256>>>(pqh, pql, pwbh, pwbl,
                                                pbp, nullptr, pg, M, NBIG, 256);

    msda_sample<<<MTOT / QPB, 256>>>(pg, refp, pah, pal);

    gemm_bf3<<<dim3(256 / 128, mtiles), 256>>>(pah, pal, pwoh, pwol,
                                               bout, query, out, M, 256, 256);
}

// round 8
// speedup vs baseline: 1.1280x; 1.1280x over previous
#include <cuda_runtime.h>
#include <cuda_bf16.h>
#include <cuda_fp16.h>
#include <mma.h>
#include <cstdint>

using namespace nvcuda;

// ---------------------------------------------------------------------------
// Problem constants
// ---------------------------------------------------------------------------
#define EMBED   256
#define HEADS   8
#define LEVELS  4
#define POINTS  4
#define DIM     32
#define BS      2
#define NQ      13294
#define MTOT    (BS * NQ)       // 26588
#define NBIG    640             // value(256) | off(256) | attn(128)

__device__ __forceinline__ int lvl_H(int l) { return l == 0 ? 100 : l == 1 ? 50 : l == 2 ? 25 : 13; }
__device__ __forceinline__ int lvl_W(int l) { return l == 0 ? 100 : l == 1 ? 50 : l == 2 ? 25 : 13; }
__device__ __forceinline__ int lvl_S(int l) { return l == 0 ? 0 : l == 1 ? 10000 : l == 2 ? 12500 : 13125; }

// ---------------------------------------------------------------------------
// Scratch
// ---------------------------------------------------------------------------
__device__ float          g_big  [(size_t)MTOT * NBIG];  // off|attn used (cols 256..640)
__device__ __half         g_val16[(size_t)MTOT * 256];   // value projection, fp16
__device__ __nv_bfloat16  g_qhi  [(size_t)MTOT * 256];
__device__ __nv_bfloat16  g_qlo  [(size_t)MTOT * 256];
__device__ __nv_bfloat16  g_ahi  [(size_t)MTOT * 256];   // sampler output hi
__device__ __nv_bfloat16  g_alo  [(size_t)MTOT * 256];   // sampler output lo
__device__ __nv_bfloat16  g_Wbh  [256 * NBIG];
__device__ __nv_bfloat16  g_Wbl  [256 * NBIG];
__device__ __nv_bfloat16  g_Woh  [256 * 256];
__device__ __nv_bfloat16  g_Wol  [256 * 256];
__device__ float          g_bp   [NBIG];

// ---------------------------------------------------------------------------
// Helpers
// ---------------------------------------------------------------------------
__device__ __forceinline__ void bf16split(float x, __nv_bfloat16& h, __nv_bfloat16& l) {
    h = __float2bfloat16(x);
    l = __float2bfloat16(x - __bfloat162float(h));
}
__device__ __forceinline__ uint32_t pack2(__nv_bfloat16 a, __nv_bfloat16 b) {
    __nv_bfloat162 t(a, b);
    return *reinterpret_cast<uint32_t*>(&t);
}
__device__ __forceinline__ void cp16(uint32_t dst, const void* src, int sz) {
    asm volatile("cp.async.cg.shared.global [%0], [%1], 16, %2;\n"
                 :: "r"(dst), "l"(src), "r"(sz) : "memory");
}
#define CP_COMMIT() asm volatile("cp.async.commit_group;" ::: "memory")
#define CP_WAIT1()  asm volatile("cp.async.wait_group 1;" ::: "memory")
#define CP_WAIT0()  asm volatile("cp.async.wait_group 0;" ::: "memory")

// ---------------------------------------------------------------------------
// Pack weights into bf16 hi/lo
// ---------------------------------------------------------------------------
__global__ void pack_weights(const float* __restrict__ Wv, const float* __restrict__ bv,
                             const float* __restrict__ Wo, const float* __restrict__ bo,
                             const float* __restrict__ Wa, const float* __restrict__ ba,
                             const float* __restrict__ Wout,
                             __nv_bfloat16* __restrict__ Wbh, __nv_bfloat16* __restrict__ Wbl,
                             __nv_bfloat16* __restrict__ Woh, __nv_bfloat16* __restrict__ Wol,
                             float* __restrict__ bp)
{
    const int i = blockIdx.x * 256 + threadIdx.x;
    if (i < 256 * NBIG) {
        const int r = i / NBIG, c = i - r * NBIG;
        float w;
        if (c < 256)      w = Wv[r * 256 + c];
        else if (c < 512) w = Wo[r * 256 + (c - 256)];
        else              w = Wa[r * 128 + (c - 512)];
        __nv_bfloat16 h, l; bf16split(w, h, l);
        Wbh[i] = h; Wbl[i] = l;
    }
    if (i < 256 * 256) {
        __nv_bfloat16 h, l; bf16split(Wout[i], h, l);
        Woh[i] = h; Wol[i] = l;
    }
    if (i < NBIG) bp[i] = (i < 256) ? bv[i] : (i < 512) ? bo[i - 256] : ba[i - 512];
}

// ---------------------------------------------------------------------------
// query fp32 -> bf16 hi/lo
// ---------------------------------------------------------------------------
__global__ void convert_query(const float4* __restrict__ q,
                              __nv_bfloat16* __restrict__ qh,
                              __nv_bfloat16* __restrict__ ql)
{
    const int i = blockIdx.x * 256 + threadIdx.x;
    const float4 v = q[i];
    __nv_bfloat16 h0, h1, h2, h3, l0, l1, l2, l3;
    bf16split(v.x, h0, l0); bf16split(v.y, h1, l1);
    bf16split(v.z, h2, l2); bf16split(v.w, h3, l3);
    reinterpret_cast<uint2*>(qh)[i] = make_uint2(pack2(h0, h1), pack2(h2, h3));
    reinterpret_cast<uint2*>(ql)[i] = make_uint2(pack2(l0, l1), pack2(l2, l3));
}

// ---------------------------------------------------------------------------
// Tensor-core GEMM, 3-pass bf16 split. Fragments loaded once per k-iter.
// Epilogue: if Vout set, columns < 256 are emitted as fp16 to Vout[row*256+col]
// (value tensor for the sampler); other columns go to C as fp32.
// ---------------------------------------------------------------------------
#define LDA 24
#define LDB 136
#define A_BUF_BYTES (128 * LDA * 2)   // 6144
#define B_BUF_BYTES (16 * LDB * 2)    // 4352
#define OFF_AH 0
#define OFF_AL (2 * A_BUF_BYTES)
#define OFF_BH (4 * A_BUF_BYTES)
#define OFF_BL (OFF_BH + 2 * B_BUF_BYTES)
#define SMEM_GEMM (OFF_BL + 2 * B_BUF_BYTES)   // 41984

__global__ __launch_bounds__(256, 2) void gemm_bf3(
    const __nv_bfloat16* __restrict__ Ah, const __nv_bfloat16* __restrict__ Al,
    const __nv_bfloat16* __restrict__ Bh, const __nv_bfloat16* __restrict__ Bl,
    const float* __restrict__ bias, const float* __restrict__ resid,
    float* __restrict__ C, __half* __restrict__ Vout, int M, int N, int K)
{
    __shared__ char smem[SMEM_GEMM];
    const uint32_t sbase = (uint32_t)__cvta_generic_to_shared(smem);

    const int t    = threadIdx.x;
    const int w    = t >> 5;
    const int lane = t & 31;
    const int wm   = w >> 2;
    const int wn   = w & 3;
    const int gn   = blockIdx.x * 128;
    const int gm   = blockIdx.y * 128;

    const int arow  = t >> 1;
    const int apart = (t & 1) * 8;
    const int ga    = min(gm + arow, M - 1);
    const int apred = (gm + arow < M) ? 16 : 0;
    const int brow  = t >> 4;
    const int bcol  = (t & 15) * 8;

    const uint32_t dAh = sbase + OFF_AH + (uint32_t)(arow * LDA + apart) * 2;
    const uint32_t dAl = sbase + OFF_AL + (uint32_t)(arow * LDA + apart) * 2;
    const uint32_t dBh = sbase + OFF_BH + (uint32_t)(brow * LDB + bcol) * 2;
    const uint32_t dBl = sbase + OFF_BL + (uint32_t)(brow * LDB + bcol) * 2;

    wmma::fragment<wmma::accumulator, 16, 16, 16, float> acc[4][2];
#pragma unroll
    for (int i = 0; i < 4; i++)
#pragma unroll
        for (int j = 0; j < 2; j++) wmma::fill_fragment(acc[i][j], 0.f);

    cp16(dAh, Ah + (size_t)ga * K + apart, apred);
    cp16(dAl, Al + (size_t)ga * K + apart, apred);
    cp16(dBh, Bh + (size_t)brow * N + gn + bcol, 16);
    cp16(dBl, Bl + (size_t)brow * N + gn + bcol, 16);
    CP_COMMIT();

    const int niter = K / 16;
    int buf = 0;
    for (int it = 0; it < niter; it++) {
        if (it + 1 < niter) {
            const int kt = (it + 1) * 16;
            const uint32_t bo = (buf ^ 1);
            cp16(dAh + bo * A_BUF_BYTES, Ah + (size_t)ga * K + kt + apart, apred);
            cp16(dAl + bo * A_BUF_BYTES, Al + (size_t)ga * K + kt + apart, apred);
            cp16(dBh + bo * B_BUF_BYTES, Bh + (size_t)(kt + brow) * N + gn + bcol, 16);
            cp16(dBl + bo * B_BUF_BYTES, Bl + (size_t)(kt + brow) * N + gn + bcol, 16);
            CP_COMMIT();
            CP_WAIT1();
        } else {
            CP_WAIT0();
        }
        __syncthreads();

        const __nv_bfloat16* pAh = reinterpret_cast<const __nv_bfloat16*>(smem + OFF_AH + buf * A_BUF_BYTES) + wm * 64 * LDA;
        const __nv_bfloat16* pAl = reinterpret_cast<const __nv_bfloat16*>(smem + OFF_AL + buf * A_BUF_BYTES) + wm * 64 * LDA;
        const __nv_bfloat16* pBh = reinterpret_cast<const __nv_bfloat16*>(smem + OFF_BH + buf * B_BUF_BYTES) + wn * 32;
        const __nv_bfloat16* pBl = reinterpret_cast<const __nv_bfloat16*>(smem + OFF_BL + buf * B_BUF_BYTES) + wn * 32;

        wmma::fragment<wmma::matrix_a, 16, 16, 16, __nv_bfloat16, wmma::row_major> ah[4], al4[4];
        wmma::fragment<wmma::matrix_b, 16, 16, 16, __nv_bfloat16, wmma::row_major> bh2[2], bl2[2];

#pragma unroll
        for (int i = 0; i < 4; i++) wmma::load_matrix_sync(ah[i],  pAh + i * 16 * LDA, LDA);
#pragma unroll
        for (int i = 0; i < 4; i++) wmma::load_matrix_sync(al4[i], pAl + i * 16 * LDA, LDA);
#pragma unroll
        for (int j = 0; j < 2; j++) wmma::load_matrix_sync(bh2[j], pBh + j * 16, LDB);
#pragma unroll
        for (int j = 0; j < 2; j++) wmma::load_matrix_sync(bl2[j], pBl + j * 16, LDB);

#pragma unroll
        for (int i = 0; i < 4; i++)
#pragma unroll
            for (int j = 0; j < 2; j++) wmma::mma_sync(acc[i][j], ah[i],  bh2[j], acc[i][j]);
#pragma unroll
        for (int i = 0; i < 4; i++)
#pragma unroll
            for (int j = 0; j < 2; j++) wmma::mma_sync(acc[i][j], ah[i],  bl2[j], acc[i][j]);
#pragma unroll
        for (int i = 0; i < 4; i++)
#pragma unroll
            for (int j = 0; j < 2; j++) wmma::mma_sync(acc[i][j], al4[i], bh2[j], acc[i][j]);

        __syncthreads();
        buf ^= 1;
    }

    // epilogue via per-warp smem staging
    float* stg = reinterpret_cast<float*>(smem) + w * 256;
    const int r  = lane >> 1;
    const int ch = (lane & 1) * 8;
#pragma unroll
    for (int i = 0; i < 4; i++) {
#pragma unroll
        for (int j = 0; j < 2; j++) {
            wmma::store_matrix_sync(stg, acc[i][j], 16, wmma::mem_row_major);
            __syncwarp();
            const int row = gm + wm * 64 + i * 16 + r;
            const int col = gn + wn * 32 + j * 16 + ch;
            if (row < M) {
                float4 o0 = *reinterpret_cast<const float4*>(&stg[r * 16 + ch]);
                float4 o1 = *reinterpret_cast<const float4*>(&stg[r * 16 + ch + 4]);
                const float4 bi0 = *reinterpret_cast<const float4*>(bias + col);
                const float4 bi1 = *reinterpret_cast<const float4*>(bias + col + 4);
                o0.x += bi0.x; o0.y += bi0.y; o0.z += bi0.z; o0.w += bi0.w;
                o1.x += bi1.x; o1.y += bi1.y; o1.z += bi1.z; o1.w += bi1.w;
                if (resid) {
                    const float4 r0 = *reinterpret_cast<const float4*>(resid + (size_t)row * N + col);
                    const float4 r1 = *reinterpret_cast<const float4*>(resid + (size_t)row * N + col + 4);
                    o0.x += r0.x; o0.y += r0.y; o0.z += r0.z; o0.w += r0.w;
                    o1.x += r1.x; o1.y += r1.y; o1.z += r1.z; o1.w += r1.w;
                }
                if (Vout != nullptr && col < 256) {
                    // value columns -> fp16 tensor for the sampler
                    __half2 h0 = __floats2half2_rn(o0.x, o0.y);
                    __half2 h1 = __floats2half2_rn(o0.z, o0.w);
                    __half2 h2 = __floats2half2_rn(o1.x, o1.y);
                    __half2 h3 = __floats2half2_rn(o1.z, o1.w);
                    uint4 u;
                    u.x = *reinterpret_cast<uint32_t*>(&h0);
                    u.y = *reinterpret_cast<uint32_t*>(&h1);
                    u.z = *reinterpret_cast<uint32_t*>(&h2);
                    u.w = *reinterpret_cast<uint32_t*>(&h3);
                    *reinterpret_cast<uint4*>(Vout + (size_t)row * 256 + col) = u;
                } else {
                    *reinterpret_cast<float4*>(C + (size_t)row * N + col)     = o0;
                    *reinterpret_cast<float4*>(C + (size_t)row * N + col + 4) = o1;
                }
            }
            __syncwarp();
        }
    }
}

// ---------------------------------------------------------------------------
// Sampler: phase 1 precompute -> smem; phase 2 gathers from the fp16 value
// tensor (LDG.64, half the L1 traffic of fp32).
// ---------------------------------------------------------------------------
#define QPB    4
#define HSTR   132
#define QSTR   (8 * HSTR)

__global__ __launch_bounds__(256) void msda_sample(
    const float* __restrict__ G,      // [M,640] (off|attn cols used)
    const __half* __restrict__ V,     // [M,256] fp16 value
    const float* __restrict__ refp,   // [M,4,2]
    __nv_bfloat16* __restrict__ ahi,
    __nv_bfloat16* __restrict__ alo)
{
    __shared__ float sp[QPB * QSTR];

    const int tid = threadIdx.x;
    const int m0  = blockIdx.x * QPB;
    const unsigned FULL = 0xffffffffu;

#pragma unroll
    for (int rep = 0; rep < 2; rep++) {
        const int p   = tid + rep * 256;
        const int q   = p >> 7;
        const int rem = p & 127;
        const int h   = rem >> 4;
        const int s   = rem & 15;
        const int m   = m0 + q;

        const float lg = G[m * NBIG + 512 + rem];
        float mx = lg;
#pragma unroll
        for (int o = 8; o; o >>= 1) mx = fmaxf(mx, __shfl_xor_sync(FULL, mx, o));
        const float e = expf(lg - mx);
        float sum = e;
#pragma unroll
        for (int o = 8; o; o >>= 1) sum += __shfl_xor_sync(FULL, sum, o);
        const float aw = e / sum;

        const int l = s >> 2, pp = s & 3;
        const int W = lvl_W(l), H = lvl_H(l), st = lvl_S(l);
        const float rx = refp[m * 8 + l * 2 + 0];
        const float ry = refp[m * 8 + l * 2 + 1];
        const float ox = G[m * NBIG + 256 + h * 32 + l * 8 + pp * 2 + 0];
        const float oy = G[m * NBIG + 256 + h * 32 + l * 8 + pp * 2 + 1];
        const float x = fmaf(rx, (float)W, ox) - 0.5f;
        const float y = fmaf(ry, (float)H, oy) - 0.5f;
        const float xf = floorf(x), yf = floorf(y);
        const int ix = (int)xf, iy = (int)yf;
        const float lx = x - xf, ly = y - yf;
        const bool x0ok = (ix >= 0)  & (ix < W);
        const bool x1ok = (ix >= -1) & (ix < W - 1);
        const bool y0ok = (iy >= 0)  & (iy < H);
        const bool y1ok = (iy >= -1) & (iy < H - 1);
        const float wx0 = 1.f - lx, wy0 = 1.f - ly;
        const float w00 = (x0ok & y0ok) ? wy0 * wx0 * aw : 0.f;
        const float w01 = (x1ok & y0ok) ? wy0 * lx  * aw : 0.f;
        const float w10 = (x0ok & y1ok) ? ly  * wx0 * aw : 0.f;
        const float w11 = (x1ok & y1ok) ? ly  * lx  * aw : 0.f;
        const int xc0 = min(max(ix, 0), W - 1);
        const int xc1 = min(max(ix + 1, 0), W - 1);
        const int yc0 = min(max(iy, 0), H - 1);
        const int yc1 = min(max(iy + 1, 0), H - 1);
        const int r0 = yc0 * W + st;
        const int r1 = yc1 * W + st;
        const int pA = (r0 + xc0) | ((r0 + xc1) << 16);
        const int pB = (r1 + xc0) | ((r1 + xc1) << 16);

        float* dst = &sp[q * QSTR + h * HSTR + s * 8];
        dst[0] = __int_as_float(pA);
        dst[1] = __int_as_float(pB);
        dst[2] = w00; dst[3] = w01; dst[4] = w10; dst[5] = w11;
    }
    __syncthreads();

    const int w    = tid >> 5;
    const int lane = tid & 31;
    const int q    = w >> 1;
    const int head = (w & 1) * 4 + (lane >> 3);
    const int c4   = (lane & 7) * 4;
    const int m    = m0 + q;
    const int b    = (m >= NQ) ? 1 : 0;

    const __half* __restrict__ vb = V + (size_t)b * NQ * 256 + head * 32 + c4;
    const float* __restrict__ prm = &sp[q * QSTR + head * HSTR];

    float4 av = make_float4(0.f, 0.f, 0.f, 0.f);
#pragma unroll
    for (int s = 0; s < 16; s++) {
        const float4 f1 = *reinterpret_cast<const float4*>(&prm[s * 8]);
        const float4 f2 = *reinterpret_cast<const float4*>(&prm[s * 8 + 4]);
        const int ia = __float_as_int(f1.x);
        const int ib = __float_as_int(f1.y);
        const uint2 u0 = *reinterpret_cast<const uint2*>(vb + (ia & 0xffff) * 256);
        const uint2 u1 = *reinterpret_cast<const uint2*>(vb + (ia >> 16)    * 256);
        const uint2 u2 = *reinterpret_cast<const uint2*>(vb + (ib & 0xffff) * 256);
        const uint2 u3 = *reinterpret_cast<const uint2*>(vb + (ib >> 16)    * 256);

        const float2 a0 = __half22float2(*reinterpret_cast<const __half2*>(&u0.x));
        const float2 a1 = __half22float2(*reinterpret_cast<const __half2*>(&u0.y));
        const float2 b0 = __half22float2(*reinterpret_cast<const __half2*>(&u1.x));
        const float2 b1 = __half22float2(*reinterpret_cast<const __half2*>(&u1.y));
        const float2 c0 = __half22float2(*reinterpret_cast<const __half2*>(&u2.x));
        const float2 c1 = __half22float2(*reinterpret_cast<const __half2*>(&u2.y));
        const float2 d0 = __half22float2(*reinterpret_cast<const __half2*>(&u3.x));
        const float2 d1 = __half22float2(*reinterpret_cast<const __half2*>(&u3.y));

        av.x = fmaf(f1.z, a0.x, av.x); av.y = fmaf(f1.z, a0.y, av.y);
        av.z = fmaf(f1.z, a1.x, av.z); av.w = fmaf(f1.z, a1.y, av.w);
        av.x = fmaf(f1.w, b0.x, av.x); av.y = fmaf(f1.w, b0.y, av.y);
        av.z = fmaf(f1.w, b1.x, av.z); av.w = fmaf(f1.w, b1.y, av.w);
        av.x = fmaf(f2.x, c0.x, av.x); av.y = fmaf(f2.x, c0.y, av.y);
        av.z = fmaf(f2.x, c1.x, av.z); av.w = fmaf(f2.x, c1.y, av.w);
        av.x = fmaf(f2.y, d0.x, av.x); av.y = fmaf(f2.y, d0.y, av.y);
        av.z = fmaf(f2.y, d1.x, av.z); av.w = fmaf(f2.y, d1.y, av.w);
    }

    __nv_bfloat16 h0b, h1b, h2b, h3b, l0b, l1b, l2b, l3b;
    bf16split(av.x, h0b, l0b); bf16split(av.y, h1b, l1b);
    bf16split(av.z, h2b, l2b); bf16split(av.w, h3b, l3b);
    const size_t base = ((size_t)m * 256 + head * 32 + c4) >> 2;
    reinterpret_cast<uint2*>(ahi)[base] = make_uint2(pack2(h0b, h1b), pack2(h2b, h3b));
    reinterpret_cast<uint2*>(alo)[base] = make_uint2(pack2(l0b, l1b), pack2(l2b, l3b));
}

// ---------------------------------------------------------------------------
// Launch
// ---------------------------------------------------------------------------
extern "C" void kernel_launch(void* const* d_in, const int* in_sizes, int n_in,
                              void* d_out, int out_size)
{
    const float* query = (const float*)d_in[0];
    const float* refp  = (const float*)d_in[1];
    const float* Wv    = (const float*)d_in[3];
    const float* bv    = (const float*)d_in[4];
    const float* Wo    = (const float*)d_in[5];
    const float* bo    = (const float*)d_in[6];
    const float* Wa    = (const float*)d_in[7];
    const float* ba    = (const float*)d_in[8];
    const float* Wout  = (const float*)d_in[9];
    const float* bout  = (const float*)d_in[10];
    float*       out   = (float*)d_out;

    float *pg, *pbp;
    __half *pv16;
    __nv_bfloat16 *pqh, *pql, *pah, *pal, *pwbh, *pwbl, *pwoh, *pwol;
    cudaGetSymbolAddress((void**)&pg,   g_big);
    cudaGetSymbolAddress((void**)&pv16, g_val16);
    cudaGetSymbolAddress((void**)&pbp,  g_bp);
    cudaGetSymbolAddress((void**)&pqh,  g_qhi);
    cudaGetSymbolAddress((void**)&pql,  g_qlo);
    cudaGetSymbolAddress((void**)&pah,  g_ahi);
    cudaGetSymbolAddress((void**)&pal,  g_alo);
    cudaGetSymbolAddress((void**)&pwbh, g_Wbh);
    cudaGetSymbolAddress((void**)&pwbl, g_Wbl);
    cudaGetSymbolAddress((void**)&pwoh, g_Woh);
    cudaGetSymbolAddress((void**)&pwol, g_Wol);

    const int M = MTOT;
    const int mtiles = (M + 127) / 128;

    pack_weights<<<NBIG, 256>>>(Wv, bv, Wo, bo, Wa, ba, Wout,
                                pwbh, pwbl, pwoh, pwol, pbp);
    convert_query<<<MTOT / 4, 256>>>((const float4*)query, pqh, pql);

    // fused projection: value cols -> fp16 Vout, off/attn cols -> fp32 g_big
    gemm_bf3<<<dim3(NBIG / 128, mtiles), 256>>>(pqh, pql, pwbh, pwbl,
                                                pbp, nullptr, pg, pv16, M, NBIG, 256);

    msda_sample<<<MTOT / QPB, 256>>>(pg, pv16, refp, pah, pal);

    gemm_bf3<<<dim3(256 / 128, mtiles), 256>>>(pah, pal, pwoh, pwol,
                                               bout, query, out, nullptr, M, 256, 256);
}

// round 10
// speedup vs baseline: 1.7229x; 1.5275x over previous
#include <cuda_runtime.h>
#include <cuda_fp16.h>
#include <mma.h>
#include <cstdint>

using namespace nvcuda;

// ---------------------------------------------------------------------------
// Problem constants
// ---------------------------------------------------------------------------
#define EMBED   256
#define HEADS   8
#define LEVELS  4
#define POINTS  4
#define DIM     32
#define BS      2
#define NQ      13294
#define MTOT    (BS * NQ)       // 26588
#define NBIG    640             // value(256) | off(256) | attn(128)

__device__ __forceinline__ int lvl_H(int l) { return l == 0 ? 100 : l == 1 ? 50 : l == 2 ? 25 : 13; }
__device__ __forceinline__ int lvl_W(int l) { return l == 0 ? 100 : l == 1 ? 50 : l == 2 ? 25 : 13; }
__device__ __forceinline__ int lvl_S(int l) { return l == 0 ? 0 : l == 1 ? 10000 : l == 2 ? 12500 : 13125; }

// ---------------------------------------------------------------------------
// Scratch
// ---------------------------------------------------------------------------
__device__ float  g_big  [(size_t)MTOT * NBIG];  // off|attn cols (256..640) fp32
__device__ __half g_val16[(size_t)MTOT * 256];   // value projection, fp16
__device__ __half g_q16  [(size_t)MTOT * 256];   // query, fp16
__device__ __half g_a16  [(size_t)MTOT * 256];   // sampler output, fp16
__device__ __half g_Wb16 [256 * NBIG];           // packed Wv|Woff|Wattn, fp16
__device__ __half g_Wo16 [256 * 256];            // Wout, fp16
__device__ float  g_bp   [NBIG];

// ---------------------------------------------------------------------------
// Helpers
// ---------------------------------------------------------------------------
__device__ __forceinline__ void cp16(uint32_t dst, const void* src, int sz) {
    asm volatile("cp.async.cg.shared.global [%0], [%1], 16, %2;\n"
                 :: "r"(dst), "l"(src), "r"(sz) : "memory");
}
#define CP_COMMIT() asm volatile("cp.async.commit_group;" ::: "memory")
#define CP_WAIT1()  asm volatile("cp.async.wait_group 1;" ::: "memory")
#define CP_WAIT0()  asm volatile("cp.async.wait_group 0;" ::: "memory")

// ---------------------------------------------------------------------------
// Pack weights to fp16:  Wbig = Wv|Woff|Wattn [256,640], Wout [256,256]
// ---------------------------------------------------------------------------
__global__ void pack_weights(const float* __restrict__ Wv, const float* __restrict__ bv,
                             const float* __restrict__ Wo, const float* __restrict__ bo,
                             const float* __restrict__ Wa, const float* __restrict__ ba,
                             const float* __restrict__ Wout,
                             __half* __restrict__ Wb16, __half* __restrict__ Wo16,
                             float* __restrict__ bp)
{
    const int i = blockIdx.x * 256 + threadIdx.x;
    if (i < 256 * NBIG) {
        const int r = i / NBIG, c = i - r * NBIG;
        float w;
        if (c < 256)      w = Wv[r * 256 + c];
        else if (c < 512) w = Wo[r * 256 + (c - 256)];
        else              w = Wa[r * 128 + (c - 512)];
        Wb16[i] = __float2half_rn(w);
    }
    if (i < 256 * 256) Wo16[i] = __float2half_rn(Wout[i]);
    if (i < NBIG) bp[i] = (i < 256) ? bv[i] : (i < 512) ? bo[i - 256] : ba[i - 512];
}

// ---------------------------------------------------------------------------
// query fp32 -> fp16
// ---------------------------------------------------------------------------
__global__ void convert_query(const float4* __restrict__ q, __half* __restrict__ q16)
{
    const int i = blockIdx.x * 256 + threadIdx.x;   // < MTOT*64
    const float4 v = q[i];
    __half2 h0 = __floats2half2_rn(v.x, v.y);
    __half2 h1 = __floats2half2_rn(v.z, v.w);
    reinterpret_cast<uint2*>(q16)[i] =
        make_uint2(*reinterpret_cast<uint32_t*>(&h0), *reinterpret_cast<uint32_t*>(&h1));
}

// ---------------------------------------------------------------------------
// Single-pass fp16 tensor-core GEMM (fp32 accumulate):
//   C = A @ B + bias (+ resid)
// A: [M,K] fp16 row-major; B: [K,N] fp16 row-major.
// Epilogue: if Vout set, cols < 256 are written fp16 to Vout; else fp32 to C.
// 128x128 tile, BK=16, 256 threads (8 warps of 64x32), cp.async double buffer.
// ---------------------------------------------------------------------------
#define LDA 24     // elems; 48B rows
#define LDB 136    // elems; 272B rows
#define A_BUF_BYTES (128 * LDA * 2)   // 6144
#define B_BUF_BYTES (16 * LDB * 2)    // 4352
#define OFF_A 0
#define OFF_B (2 * A_BUF_BYTES)              // 12288
#define SMEM_GEMM (OFF_B + 2 * B_BUF_BYTES)  // 20992

__global__ __launch_bounds__(256, 2) void gemm_fp16(
    const __half* __restrict__ A, const __half* __restrict__ B,
    const float* __restrict__ bias, const float* __restrict__ resid,
    float* __restrict__ C, __half* __restrict__ Vout, int M, int N, int K)
{
    __shared__ char smem[SMEM_GEMM];
    const uint32_t sbase = (uint32_t)__cvta_generic_to_shared(smem);

    const int t    = threadIdx.x;
    const int w    = t >> 5;
    const int lane = t & 31;
    const int wm   = w >> 2;          // 0..1
    const int wn   = w & 3;           // 0..3
    const int gn   = blockIdx.x * 128;
    const int gm   = blockIdx.y * 128;

    const int arow  = t >> 1;
    const int apart = (t & 1) * 8;
    const int ga    = min(gm + arow, M - 1);
    const int apred = (gm + arow < M) ? 16 : 0;
    const int brow  = t >> 4;
    const int bcol  = (t & 15) * 8;

    const uint32_t dA = sbase + OFF_A + (uint32_t)(arow * LDA + apart) * 2;
    const uint32_t dB = sbase + OFF_B + (uint32_t)(brow * LDB + bcol) * 2;

    wmma::fragment<wmma::accumulator, 16, 16, 16, float> acc[4][2];
#pragma unroll
    for (int i = 0; i < 4; i++)
#pragma unroll
        for (int j = 0; j < 2; j++) wmma::fill_fragment(acc[i][j], 0.f);

    cp16(dA, A + (size_t)ga * K + apart, apred);
    cp16(dB, B + (size_t)brow * N + gn + bcol, 16);
    CP_COMMIT();

    const int niter = K / 16;
    int buf = 0;
    for (int it = 0; it < niter; it++) {
        if (it + 1 < niter) {
            const int kt = (it + 1) * 16;
            const uint32_t bo = (buf ^ 1);
            cp16(dA + bo * A_BUF_BYTES, A + (size_t)ga * K + kt + apart, apred);
            cp16(dB + bo * B_BUF_BYTES, B + (size_t)(kt + brow) * N + gn + bcol, 16);
            CP_COMMIT();
            CP_WAIT1();
        } else {
            CP_WAIT0();
        }
        __syncthreads();

        const __half* pA = reinterpret_cast<const __half*>(smem + OFF_A + buf * A_BUF_BYTES) + wm * 64 * LDA;
        const __half* pB = reinterpret_cast<const __half*>(smem + OFF_B + buf * B_BUF_BYTES) + wn * 32;

        wmma::fragment<wmma::matrix_a, 16, 16, 16, __half, wmma::row_major> af[4];
        wmma::fragment<wmma::matrix_b, 16, 16, 16, __half, wmma::row_major> bf[2];

#pragma unroll
        for (int i = 0; i < 4; i++) wmma::load_matrix_sync(af[i], pA + i * 16 * LDA, LDA);
#pragma unroll
        for (int j = 0; j < 2; j++) wmma::load_matrix_sync(bf[j], pB + j * 16, LDB);

#pragma unroll
        for (int i = 0; i < 4; i++)
#pragma unroll
            for (int j = 0; j < 2; j++) wmma::mma_sync(acc[i][j], af[i], bf[j], acc[i][j]);

        __syncthreads();
        buf ^= 1;
    }

    // epilogue via per-warp smem staging
    float* stg = reinterpret_cast<float*>(smem) + w * 256;
    const int r  = lane >> 1;
    const int ch = (lane & 1) * 8;
#pragma unroll
    for (int i = 0; i < 4; i++) {
#pragma unroll
        for (int j = 0; j < 2; j++) {
            wmma::store_matrix_sync(stg, acc[i][j], 16, wmma::mem_row_major);
            __syncwarp();
            const int row = gm + wm * 64 + i * 16 + r;
            const int col = gn + wn * 32 + j * 16 + ch;
            if (row < M) {
                float4 o0 = *reinterpret_cast<const float4*>(&stg[r * 16 + ch]);
                float4 o1 = *reinterpret_cast<const float4*>(&stg[r * 16 + ch + 4]);
                const float4 bi0 = *reinterpret_cast<const float4*>(bias + col);
                const float4 bi1 = *reinterpret_cast<const float4*>(bias + col + 4);
                o0.x += bi0.x; o0.y += bi0.y; o0.z += bi0.z; o0.w += bi0.w;
                o1.x += bi1.x; o1.y += bi1.y; o1.z += bi1.z; o1.w += bi1.w;
                if (resid) {
                    const float4 r0 = *reinterpret_cast<const float4*>(resid + (size_t)row * N + col);
                    const float4 r1 = *reinterpret_cast<const float4*>(resid + (size_t)row * N + col + 4);
                    o0.x += r0.x; o0.y += r0.y; o0.z += r0.z; o0.w += r0.w;
                    o1.x += r1.x; o1.y += r1.y; o1.z += r1.z; o1.w += r1.w;
                }
                if (Vout != nullptr && col < 256) {
                    __half2 h0 = __floats2half2_rn(o0.x, o0.y);
                    __half2 h1 = __floats2half2_rn(o0.z, o0.w);
                    __half2 h2 = __floats2half2_rn(o1.x, o1.y);
                    __half2 h3 = __floats2half2_rn(o1.z, o1.w);
                    uint4 u;
                    u.x = *reinterpret_cast<uint32_t*>(&h0);
                    u.y = *reinterpret_cast<uint32_t*>(&h1);
                    u.z = *reinterpret_cast<uint32_t*>(&h2);
                    u.w = *reinterpret_cast<uint32_t*>(&h3);
                    *reinterpret_cast<uint4*>(Vout + (size_t)row * 256 + col) = u;
                } else {
                    *reinterpret_cast<float4*>(C + (size_t)row * N + col)     = o0;
                    *reinterpret_cast<float4*>(C + (size_t)row * N + col + 4) = o1;
                }
            }
            __syncwarp();
        }
    }
}

// ---------------------------------------------------------------------------
// Sampler: phase 1 precompute -> smem; phase 2 fp16 gathers (LDG.64).
// Output written as fp16 for the second GEMM.
// ---------------------------------------------------------------------------
#define QPB    4
#define HSTR   132
#define QSTR   (8 * HSTR)

__global__ __launch_bounds__(256) void msda_sample(
    const float* __restrict__ G,      // [M,640] (off|attn cols used)
    const __half* __restrict__ V,     // [M,256] fp16 value
    const float* __restrict__ refp,   // [M,4,2]
    __half* __restrict__ aout)        // [M,256] fp16
{
    __shared__ float sp[QPB * QSTR];

    const int tid = threadIdx.x;
    const int m0  = blockIdx.x * QPB;
    const unsigned FULL = 0xffffffffu;

#pragma unroll
    for (int rep = 0; rep < 2; rep++) {
        const int p   = tid + rep * 256;
        const int q   = p >> 7;
        const int rem = p & 127;
        const int h   = rem >> 4;
        const int s   = rem & 15;
        const int m   = m0 + q;

        const float lg = G[m * NBIG + 512 + rem];
        float mx = lg;
#pragma unroll
        for (int o = 8; o; o >>= 1) mx = fmaxf(mx, __shfl_xor_sync(FULL, mx, o));
        const float e = expf(lg - mx);
        float sum = e;
#pragma unroll
        for (int o = 8; o; o >>= 1) sum += __shfl_xor_sync(FULL, sum, o);
        const float aw = e / sum;

        const int l = s >> 2, pp = s & 3;
        const int W = lvl_W(l), H = lvl_H(l), st = lvl_S(l);
        const float rx = refp[m * 8 + l * 2 + 0];
        const float ry = refp[m * 8 + l * 2 + 1];
        const float ox = G[m * NBIG + 256 + h * 32 + l * 8 + pp * 2 + 0];
        const float oy = G[m * NBIG + 256 + h * 32 + l * 8 + pp * 2 + 1];
        const float x = fmaf(rx, (float)W, ox) - 0.5f;
        const float y = fmaf(ry, (float)H, oy) - 0.5f;
        const float xf = floorf(x), yf = floorf(y);
        const int ix = (int)xf, iy = (int)yf;
        const float lx = x - xf, ly = y - yf;
        const bool x0ok = (ix >= 0)  & (ix < W);
        const bool x1ok = (ix >= -1) & (ix < W - 1);
        const bool y0ok = (iy >= 0)  & (iy < H);
        const bool y1ok = (iy >= -1) & (iy < H - 1);
        const float wx0 = 1.f - lx, wy0 = 1.f - ly;
        const float w00 = (x0ok & y0ok) ? wy0 * wx0 * aw : 0.f;
        const float w01 = (x1ok & y0ok) ? wy0 * lx  * aw : 0.f;
        const float w10 = (x0ok & y1ok) ? ly  * wx0 * aw : 0.f;
        const float w11 = (x1ok & y1ok) ? ly  * lx  * aw : 0.f;
        const int xc0 = min(max(ix, 0), W - 1);
        const int xc1 = min(max(ix + 1, 0), W - 1);
        const int yc0 = min(max(iy, 0), H - 1);
        const int yc1 = min(max(iy + 1, 0), H - 1);
        const int r0 = yc0 * W + st;
        const int r1 = yc1 * W + st;
        const int pA = (r0 + xc0) | ((r0 + xc1) << 16);
        const int pB = (r1 + xc0) | ((r1 + xc1) << 16);

        float* dst = &sp[q * QSTR + h * HSTR + s * 8];
        dst[0] = __int_as_float(pA);
        dst[1] = __int_as_float(pB);
        dst[2] = w00; dst[3] = w01; dst[4] = w10; dst[5] = w11;
    }
    __syncthreads();

    const int w    = tid >> 5;
    const int lane = tid & 31;
    const int q    = w >> 1;
    const int head = (w & 1) * 4 + (lane >> 3);
    const int c4   = (lane & 7) * 4;
    const int m    = m0 + q;
    const int b    = (m >= NQ) ? 1 : 0;

    const __half* __restrict__ vb = V + (size_t)b * NQ * 256 + head * 32 + c4;
    const float* __restrict__ prm = &sp[q * QSTR + head * HSTR];

    float4 av = make_float4(0.f, 0.f, 0.f, 0.f);
#pragma unroll
    for (int s = 0; s < 16; s++) {
        const float4 f1 = *reinterpret_cast<const float4*>(&prm[s * 8]);
        const float4 f2 = *reinterpret_cast<const float4*>(&prm[s * 8 + 4]);
        const int ia = __float_as_int(f1.x);
        const int ib = __float_as_int(f1.y);
        const uint2 u0 = *reinterpret_cast<const uint2*>(vb + (ia & 0xffff) * 256);
        const uint2 u1 = *reinterpret_cast<const uint2*>(vb + (ia >> 16)    * 256);
        const uint2 u2 = *reinterpret_cast<const uint2*>(vb + (ib & 0xffff) * 256);
        const uint2 u3 = *reinterpret_cast<const uint2*>(vb + (ib >> 16)    * 256);

        const float2 a0 = __half22float2(*reinterpret_cast<const __half2*>(&u0.x));
        const float2 a1 = __half22float2(*reinterpret_cast<const __half2*>(&u0.y));
        const float2 b0 = __half22float2(*reinterpret_cast<const __half2*>(&u1.x));
        const float2 b1 = __half22float2(*reinterpret_cast<const __half2*>(&u1.y));
        const float2 c0 = __half22float2(*reinterpret_cast<const __half2*>(&u2.x));
        const float2 c1 = __half22float2(*reinterpret_cast<const __half2*>(&u2.y));
        const float2 d0 = __half22float2(*reinterpret_cast<const __half2*>(&u3.x));
        const float2 d1 = __half22float2(*reinterpret_cast<const __half2*>(&u3.y));

        av.x = fmaf(f1.z, a0.x, av.x); av.y = fmaf(f1.z, a0.y, av.y);
        av.z = fmaf(f1.z, a1.x, av.z); av.w = fmaf(f1.z, a1.y, av.w);
        av.x = fmaf(f1.w, b0.x, av.x); av.y = fmaf(f1.w, b0.y, av.y);
        av.z = fmaf(f1.w, b1.x, av.z); av.w = fmaf(f1.w, b1.y, av.w);
        av.x = fmaf(f2.x, c0.x, av.x); av.y = fmaf(f2.x, c0.y, av.y);
        av.z = fmaf(f2.x, c1.x, av.z); av.w = fmaf(f2.x, c1.y, av.w);
        av.x = fmaf(f2.y, d0.x, av.x); av.y = fmaf(f2.y, d0.y, av.y);
        av.z = fmaf(f2.y, d1.x, av.z); av.w = fmaf(f2.y, d1.y, av.w);
    }

    __half2 h0 = __floats2half2_rn(av.x, av.y);
    __half2 h1 = __floats2half2_rn(av.z, av.w);
    const size_t base = ((size_t)m * 256 + head * 32 + c4) >> 2;
    reinterpret_cast<uint2*>(aout)[base] =
        make_uint2(*reinterpret_cast<uint32_t*>(&h0), *reinterpret_cast<uint32_t*>(&h1));
}

// ---------------------------------------------------------------------------
// Launch
// ---------------------------------------------------------------------------
extern "C" void kernel_launch(void* const* d_in, const int* in_sizes, int n_in,
                              void* d_out, int out_size)
{
    const float* query = (const float*)d_in[0];
    const float* refp  = (const float*)d_in[1];
    const float* Wv    = (const float*)d_in[3];
    const float* bv    = (const float*)d_in[4];
    const float* Wo    = (const float*)d_in[5];
    const float* bo    = (const float*)d_in[6];
    const float* Wa    = (const float*)d_in[7];
    const float* ba    = (const float*)d_in[8];
    const float* Wout  = (const float*)d_in[9];
    const float* bout  = (const float*)d_in[10];
    float*       out   = (float*)d_out;

    float *pg, *pbp;
    __half *pv16, *pq16, *pa16, *pwb16, *pwo16;
    cudaGetSymbolAddress((void**)&pg,    g_big);
    cudaGetSymbolAddress((void**)&pv16,  g_val16);
    cudaGetSymbolAddress((void**)&pq16,  g_q16);
    cudaGetSymbolAddress((void**)&pa16,  g_a16);
    cudaGetSymbolAddress((void**)&pwb16, g_Wb16);
    cudaGetSymbolAddress((void**)&pwo16, g_Wo16);
    cudaGetSymbolAddress((void**)&pbp,   g_bp);

    const int M = MTOT;
    const int mtiles = (M + 127) / 128;

    pack_weights<<<NBIG, 256>>>(Wv, bv, Wo, bo, Wa, ba, Wout, pwb16, pwo16, pbp);
    convert_query<<<MTOT / 4, 256>>>((const float4*)query, pq16);

    // fused projection: value cols -> fp16 Vout, off/attn cols -> fp32 g_big
    gemm_fp16<<<dim3(NBIG / 128, mtiles), 256>>>(pq16, pwb16, pbp, nullptr,
                                                 pg, pv16, M, NBIG, 256);

    msda_sample<<<MTOT / QPB, 256>>>(pg, pv16, refp, pa16);

    // output projection + bias + residual
    gemm_fp16<<<dim3(256 / 128, mtiles), 256>>>(pa16, pwo16, bout, query,
                                                out, nullptr, M, 256, 256);
}

// round 11
// speedup vs baseline: 1.8279x; 1.0609x over previous
#include <cuda_runtime.h>
#include <cuda_fp16.h>
#include <mma.h>
#include <cstdint>

using namespace nvcuda;

// ---------------------------------------------------------------------------
// Problem constants
// ---------------------------------------------------------------------------
#define EMBED   256
#define HEADS   8
#define LEVELS  4
#define POINTS  4
#define DIM     32
#define BS      2
#define NQ      13294
#define MTOT    (BS * NQ)       // 26588
#define NBIG    640             // value(256) | off(256) | attn(128)

__device__ __forceinline__ int lvl_H(int l) { return l == 0 ? 100 : l == 1 ? 50 : l == 2 ? 25 : 13; }
__device__ __forceinline__ int lvl_W(int l) { return l == 0 ? 100 : l == 1 ? 50 : l == 2 ? 25 : 13; }
__device__ __forceinline__ int lvl_S(int l) { return l == 0 ? 0 : l == 1 ? 10000 : l == 2 ? 12500 : 13125; }

// ---------------------------------------------------------------------------
// Scratch
// ---------------------------------------------------------------------------
__device__ float  g_big  [(size_t)MTOT * NBIG];  // off|attn cols (256..640) fp32
__device__ __half g_val16[(size_t)MTOT * 256];   // value projection, fp16
__device__ __half g_q16  [(size_t)MTOT * 256];   // query, fp16
__device__ __half g_a16  [(size_t)MTOT * 256];   // sampler output, fp16
__device__ __half g_Wb16 [256 * NBIG];           // packed Wv|Woff|Wattn, fp16
__device__ __half g_Wo16 [256 * 256];            // Wout, fp16
__device__ float  g_bp   [NBIG];

// ---------------------------------------------------------------------------
// Helpers
// ---------------------------------------------------------------------------
__device__ __forceinline__ void cp16(uint32_t dst, const void* src, int sz) {
    asm volatile("cp.async.cg.shared.global [%0], [%1], 16, %2;\n"
                 :: "r"(dst), "l"(src), "r"(sz) : "memory");
}
#define CP_COMMIT() asm volatile("cp.async.commit_group;" ::: "memory")
#define CP_WAIT1()  asm volatile("cp.async.wait_group 1;" ::: "memory")
#define CP_WAIT0()  asm volatile("cp.async.wait_group 0;" ::: "memory")

__device__ __forceinline__ float h2w_pack(float w) {   // broadcast fp16 weight
    __half2 p = __half2half2(__float2half_rn(w));
    return __uint_as_float(*reinterpret_cast<uint32_t*>(&p));
}

// ---------------------------------------------------------------------------
// Pack weights to fp16:  Wbig = Wv|Woff|Wattn [256,640], Wout [256,256]
// ---------------------------------------------------------------------------
__global__ void pack_weights(const float* __restrict__ Wv, const float* __restrict__ bv,
                             const float* __restrict__ Wo, const float* __restrict__ bo,
                             const float* __restrict__ Wa, const float* __restrict__ ba,
                             const float* __restrict__ Wout,
                             __half* __restrict__ Wb16, __half* __restrict__ Wo16,
                             float* __restrict__ bp)
{
    const int i = blockIdx.x * 256 + threadIdx.x;
    if (i < 256 * NBIG) {
        const int r = i / NBIG, c = i - r * NBIG;
        float w;
        if (c < 256)      w = Wv[r * 256 + c];
        else if (c < 512) w = Wo[r * 256 + (c - 256)];
        else              w = Wa[r * 128 + (c - 512)];
        Wb16[i] = __float2half_rn(w);
    }
    if (i < 256 * 256) Wo16[i] = __float2half_rn(Wout[i]);
    if (i < NBIG) bp[i] = (i < 256) ? bv[i] : (i < 512) ? bo[i - 256] : ba[i - 512];
}

// ---------------------------------------------------------------------------
// query fp32 -> fp16
// ---------------------------------------------------------------------------
__global__ void convert_query(const float4* __restrict__ q, __half* __restrict__ q16)
{
    const int i = blockIdx.x * 256 + threadIdx.x;   // < MTOT*64
    const float4 v = q[i];
    __half2 h0 = __floats2half2_rn(v.x, v.y);
    __half2 h1 = __floats2half2_rn(v.z, v.w);
    reinterpret_cast<uint2*>(q16)[i] =
        make_uint2(*reinterpret_cast<uint32_t*>(&h0), *reinterpret_cast<uint32_t*>(&h1));
}

// ---------------------------------------------------------------------------
// Single-pass fp16 tensor-core GEMM (fp32 accumulate):
//   C = A @ B + bias (+ resid)
// Epilogue: if Vout set, cols < 256 are written fp16 to Vout; else fp32 to C.
// 128x128 tile, BK=16, 256 threads (8 warps of 64x32), cp.async double buffer.
// ---------------------------------------------------------------------------
#define LDA 24     // elems; 48B rows
#define LDB 136    // elems; 272B rows
#define A_BUF_BYTES (128 * LDA * 2)   // 6144
#define B_BUF_BYTES (16 * LDB * 2)    // 4352
#define OFF_A 0
#define OFF_B (2 * A_BUF_BYTES)              // 12288
#define SMEM_GEMM (OFF_B + 2 * B_BUF_BYTES)  // 20992

__global__ __launch_bounds__(256, 2) void gemm_fp16(
    const __half* __restrict__ A, const __half* __restrict__ B,
    const float* __restrict__ bias, const float* __restrict__ resid,
    float* __restrict__ C, __half* __restrict__ Vout, int M, int N, int K)
{
    __shared__ char smem[SMEM_GEMM];
    const uint32_t sbase = (uint32_t)__cvta_generic_to_shared(smem);

    const int t    = threadIdx.x;
    const int w    = t >> 5;
    const int lane = t & 31;
    const int wm   = w >> 2;          // 0..1
    const int wn   = w & 3;           // 0..3
    const int gn   = blockIdx.x * 128;
    const int gm   = blockIdx.y * 128;

    const int arow  = t >> 1;
    const int apart = (t & 1) * 8;
    const int ga    = min(gm + arow, M - 1);
    const int apred = (gm + arow < M) ? 16 : 0;
    const int brow  = t >> 4;
    const int bcol  = (t & 15) * 8;

    const uint32_t dA = sbase + OFF_A + (uint32_t)(arow * LDA + apart) * 2;
    const uint32_t dB = sbase + OFF_B + (uint32_t)(brow * LDB + bcol) * 2;

    wmma::fragment<wmma::accumulator, 16, 16, 16, float> acc[4][2];
#pragma unroll
    for (int i = 0; i < 4; i++)
#pragma unroll
        for (int j = 0; j < 2; j++) wmma::fill_fragment(acc[i][j], 0.f);

    cp16(dA, A + (size_t)ga * K + apart, apred);
    cp16(dB, B + (size_t)brow * N + gn + bcol, 16);
    CP_COMMIT();

    const int niter = K / 16;
    int buf = 0;
    for (int it = 0; it < niter; it++) {
        if (it + 1 < niter) {
            const int kt = (it + 1) * 16;
            const uint32_t bo = (buf ^ 1);
            cp16(dA + bo * A_BUF_BYTES, A + (size_t)ga * K + kt + apart, apred);
            cp16(dB + bo * B_BUF_BYTES, B + (size_t)(kt + brow) * N + gn + bcol, 16);
            CP_COMMIT();
            CP_WAIT1();
        } else {
            CP_WAIT0();
        }
        __syncthreads();

        const __half* pA = reinterpret_cast<const __half*>(smem + OFF_A + buf * A_BUF_BYTES) + wm * 64 * LDA;
        const __half* pB = reinterpret_cast<const __half*>(smem + OFF_B + buf * B_BUF_BYTES) + wn * 32;

        wmma::fragment<wmma::matrix_a, 16, 16, 16, __half, wmma::row_major> af[4];
        wmma::fragment<wmma::matrix_b, 16, 16, 16, __half, wmma::row_major> bf[2];

#pragma unroll
        for (int i = 0; i < 4; i++) wmma::load_matrix_sync(af[i], pA + i * 16 * LDA, LDA);
#pragma unroll
        for (int j = 0; j < 2; j++) wmma::load_matrix_sync(bf[j], pB + j * 16, LDB);

#pragma unroll
        for (int i = 0; i < 4; i++)
#pragma unroll
            for (int j = 0; j < 2; j++) wmma::mma_sync(acc[i][j], af[i], bf[j], acc[i][j]);

        __syncthreads();
        buf ^= 1;
    }

    // epilogue via per-warp smem staging
    float* stg = reinterpret_cast<float*>(smem) + w * 256;
    const int r  = lane >> 1;
    const int ch = (lane & 1) * 8;
#pragma unroll
    for (int i = 0; i < 4; i++) {
#pragma unroll
        for (int j = 0; j < 2; j++) {
            wmma::store_matrix_sync(stg, acc[i][j], 16, wmma::mem_row_major);
            __syncwarp();
            const int row = gm + wm * 64 + i * 16 + r;
            const int col = gn + wn * 32 + j * 16 + ch;
            if (row < M) {
                float4 o0 = *reinterpret_cast<const float4*>(&stg[r * 16 + ch]);
                float4 o1 = *reinterpret_cast<const float4*>(&stg[r * 16 + ch + 4]);
                const float4 bi0 = *reinterpret_cast<const float4*>(bias + col);
                const float4 bi1 = *reinterpret_cast<const float4*>(bias + col + 4);
                o0.x += bi0.x; o0.y += bi0.y; o0.z += bi0.z; o0.w += bi0.w;
                o1.x += bi1.x; o1.y += bi1.y; o1.z += bi1.z; o1.w += bi1.w;
                if (resid) {
                    const float4 r0 = *reinterpret_cast<const float4*>(resid + (size_t)row * N + col);
                    const float4 r1 = *reinterpret_cast<const float4*>(resid + (size_t)row * N + col + 4);
                    o0.x += r0.x; o0.y += r0.y; o0.z += r0.z; o0.w += r0.w;
                    o1.x += r1.x; o1.y += r1.y; o1.z += r1.z; o1.w += r1.w;
                }
                if (Vout != nullptr && col < 256) {
                    __half2 h0 = __floats2half2_rn(o0.x, o0.y);
                    __half2 h1 = __floats2half2_rn(o0.z, o0.w);
                    __half2 h2 = __floats2half2_rn(o1.x, o1.y);
                    __half2 h3 = __floats2half2_rn(o1.z, o1.w);
                    uint4 u;
                    u.x = *reinterpret_cast<uint32_t*>(&h0);
                    u.y = *reinterpret_cast<uint32_t*>(&h1);
                    u.z = *reinterpret_cast<uint32_t*>(&h2);
                    u.w = *reinterpret_cast<uint32_t*>(&h3);
                    *reinterpret_cast<uint4*>(Vout + (size_t)row * 256 + col) = u;
                } else {
                    *reinterpret_cast<float4*>(C + (size_t)row * N + col)     = o0;
                    *reinterpret_cast<float4*>(C + (size_t)row * N + col + 4) = o1;
                }
            }
            __syncwarp();
        }
    }
}

// ---------------------------------------------------------------------------
// Sampler. Phase 1: per-(q,h,s) precompute -> smem: 4 UNPACKED int indices +
// 4 pre-broadcast half2 weights (32 B/sample, same footprint as before).
// Phase 2: 2 LDS.128 + 4 IMAD.WIDE-addressed LDG.64 + half2 bilinear combine
// (8 HFMA2-class) + one float accumulate per sample. No unpack shifts, no
// per-corner fp32 FMA tree.
// ---------------------------------------------------------------------------
#define QPB    4
#define HSTR   132
#define QSTR   (8 * HSTR)

__global__ __launch_bounds__(256) void msda_sample(
    const float* __restrict__ G,      // [M,640] (off|attn cols used)
    const __half* __restrict__ V,     // [M,256] fp16 value
    const float* __restrict__ refp,   // [M,4,2]
    __half* __restrict__ aout)        // [M,256] fp16
{
    __shared__ float sp[QPB * QSTR];

    const int tid = threadIdx.x;
    const int m0  = blockIdx.x * QPB;
    const unsigned FULL = 0xffffffffu;

#pragma unroll
    for (int rep = 0; rep < 2; rep++) {
        const int p   = tid + rep * 256;
        const int q   = p >> 7;
        const int rem = p & 127;
        const int h   = rem >> 4;
        const int s   = rem & 15;
        const int m   = m0 + q;

        const float lg = G[m * NBIG + 512 + rem];
        float mx = lg;
#pragma unroll
        for (int o = 8; o; o >>= 1) mx = fmaxf(mx, __shfl_xor_sync(FULL, mx, o));
        const float e = expf(lg - mx);
        float sum = e;
#pragma unroll
        for (int o = 8; o; o >>= 1) sum += __shfl_xor_sync(FULL, sum, o);
        const float aw = e / sum;

        const int l = s >> 2, pp = s & 3;
        const int W = lvl_W(l), H = lvl_H(l), st = lvl_S(l);
        const float rx = refp[m * 8 + l * 2 + 0];
        const float ry = refp[m * 8 + l * 2 + 1];
        const float ox = G[m * NBIG + 256 + h * 32 + l * 8 + pp * 2 + 0];
        const float oy = G[m * NBIG + 256 + h * 32 + l * 8 + pp * 2 + 1];
        const float x = fmaf(rx, (float)W, ox) - 0.5f;
        const float y = fmaf(ry, (float)H, oy) - 0.5f;
        const float xf = floorf(x), yf = floorf(y);
        const int ix = (int)xf, iy = (int)yf;
        const float lx = x - xf, ly = y - yf;
        const bool x0ok = (ix >= 0)  & (ix < W);
        const bool x1ok = (ix >= -1) & (ix < W - 1);
        const bool y0ok = (iy >= 0)  & (iy < H);
        const bool y1ok = (iy >= -1) & (iy < H - 1);
        const float wx0 = 1.f - lx, wy0 = 1.f - ly;
        const float w00 = (x0ok & y0ok) ? wy0 * wx0 * aw : 0.f;
        const float w01 = (x1ok & y0ok) ? wy0 * lx  * aw : 0.f;
        const float w10 = (x0ok & y1ok) ? ly  * wx0 * aw : 0.f;
        const float w11 = (x1ok & y1ok) ? ly  * lx  * aw : 0.f;
        const int xc0 = min(max(ix, 0), W - 1);
        const int xc1 = min(max(ix + 1, 0), W - 1);
        const int yc0 = min(max(iy, 0), H - 1);
        const int yc1 = min(max(iy + 1, 0), H - 1);
        const int r0 = yc0 * W + st;
        const int r1 = yc1 * W + st;

        float* dst = &sp[q * QSTR + h * HSTR + s * 8];
        dst[0] = __int_as_float(r0 + xc0);
        dst[1] = __int_as_float(r0 + xc1);
        dst[2] = __int_as_float(r1 + xc0);
        dst[3] = __int_as_float(r1 + xc1);
        dst[4] = h2w_pack(w00);
        dst[5] = h2w_pack(w01);
        dst[6] = h2w_pack(w10);
        dst[7] = h2w_pack(w11);
    }
    __syncthreads();

    const int w    = tid >> 5;
    const int lane = tid & 31;
    const int q    = w >> 1;
    const int head = (w & 1) * 4 + (lane >> 3);
    const int c4   = (lane & 7) * 4;
    const int m    = m0 + q;
    const int b    = (m >= NQ) ? 1 : 0;

    const __half* __restrict__ vb = V + (size_t)b * NQ * 256 + head * 32 + c4;
    const float* __restrict__ prm = &sp[q * QSTR + head * HSTR];

    float4 av = make_float4(0.f, 0.f, 0.f, 0.f);
#pragma unroll
    for (int s = 0; s < 16; s++) {
        const float4 f1 = *reinterpret_cast<const float4*>(&prm[s * 8]);     // 4 indices
        const float4 f2 = *reinterpret_cast<const float4*>(&prm[s * 8 + 4]); // 4 half2 weights

        const uint2 u0 = *reinterpret_cast<const uint2*>(vb + __float_as_int(f1.x) * 256);
        const uint2 u1 = *reinterpret_cast<const uint2*>(vb + __float_as_int(f1.y) * 256);
        const uint2 u2 = *reinterpret_cast<const uint2*>(vb + __float_as_int(f1.z) * 256);
        const uint2 u3 = *reinterpret_cast<const uint2*>(vb + __float_as_int(f1.w) * 256);

        const __half2 w0 = *reinterpret_cast<const __half2*>(&f2.x);
        const __half2 w1 = *reinterpret_cast<const __half2*>(&f2.y);
        const __half2 w2 = *reinterpret_cast<const __half2*>(&f2.z);
        const __half2 w3 = *reinterpret_cast<const __half2*>(&f2.w);

        __half2 sA = __hmul2(w0, *reinterpret_cast<const __half2*>(&u0.x));
        sA = __hfma2(w1, *reinterpret_cast<const __half2*>(&u1.x), sA);
        sA = __hfma2(w2, *reinterpret_cast<const __half2*>(&u2.x), sA);
        sA = __hfma2(w3, *reinterpret_cast<const __half2*>(&u3.x), sA);

        __half2 sB = __hmul2(w0, *reinterpret_cast<const __half2*>(&u0.y));
        sB = __hfma2(w1, *reinterpret_cast<const __half2*>(&u1.y), sB);
        sB = __hfma2(w2, *reinterpret_cast<const __half2*>(&u2.y), sB);
        sB = __hfma2(w3, *reinterpret_cast<const __half2*>(&u3.y), sB);

        const float2 rA = __half22float2(sA);
        const float2 rB = __half22float2(sB);
        av.x += rA.x; av.y += rA.y; av.z += rB.x; av.w += rB.y;
    }

    __half2 h0 = __floats2half2_rn(av.x, av.y);
    __half2 h1 = __floats2half2_rn(av.z, av.w);
    const size_t base = ((size_t)m * 256 + head * 32 + c4) >> 2;
    reinterpret_cast<uint2*>(aout)[base] =
        make_uint2(*reinterpret_cast<uint32_t*>(&h0), *reinterpret_cast<uint32_t*>(&h1));
}

// ---------------------------------------------------------------------------
// Launch
// ---------------------------------------------------------------------------
extern "C" void kernel_launch(void* const* d_in, const int* in_sizes, int n_in,
                              void* d_out, int out_size)
{
    const float* query = (const float*)d_in[0];
    const float* refp  = (const float*)d_in[1];
    const float* Wv    = (const float*)d_in[3];
    const float* bv    = (const float*)d_in[4];
    const float* Wo    = (const float*)d_in[5];
    const float* bo    = (const float*)d_in[6];
    const float* Wa    = (const float*)d_in[7];
    const float* ba    = (const float*)d_in[8];
    const float* Wout  = (const float*)d_in[9];
    const float* bout  = (const float*)d_in[10];
    float*       out   = (float*)d_out;

    float *pg, *pbp;
    __half *pv16, *pq16, *pa16, *pwb16, *pwo16;
    cudaGetSymbolAddress((void**)&pg,    g_big);
    cudaGetSymbolAddress((void**)&pv16,  g_val16);
    cudaGetSymbolAddress((void**)&pq16,  g_q16);
    cudaGetSymbolAddress((void**)&pa16,  g_a16);
    cudaGetSymbolAddress((void**)&pwb16, g_Wb16);
    cudaGetSymbolAddress((void**)&pwo16, g_Wo16);
    cudaGetSymbolAddress((void**)&pbp,   g_bp);

    const int M = MTOT;
    const int mtiles = (M + 127) / 128;

    pack_weights<<<NBIG, 256>>>(Wv, bv, Wo, bo, Wa, ba, Wout, pwb16, pwo16, pbp);
    convert_query<<<MTOT / 4, 256>>>((const float4*)query, pq16);

    // fused projection: value cols -> fp16 Vout, off/attn cols -> fp32 g_big
    gemm_fp16<<<dim3(NBIG / 128, mtiles), 256>>>(pq16, pwb16, pbp, nullptr,
                                                 pg, pv16, M, NBIG, 256);

    msda_sample<<<MTOT / QPB, 256>>>(pg, pv16, refp, pa16);

    // output projection + bias + residual
    gemm_fp16<<<dim3(256 / 128, mtiles), 256>>>(pa16, pwo16, bout, query,
                                                out, nullptr, M, 256, 256);
}